// round 7
// baseline (speedup 1.0000x reference)
#include <cuda_runtime.h>
#include <cuda_fp16.h>
#include <cstdint>

#define BB   32
#define CHN  16
#define NN   261
#define MM   256
#define MAT  (MM*MM)
#define NMAT (BB*CHN)

// ---------------- scratch (device globals; no allocs allowed) ----------------
__device__ __align__(256) __half g_Ah  [NMAT * MAT];   // feat fp16 hi (row-major)
__device__ __align__(256) __half g_Al  [NMAT * MAT];   // feat fp16 lo (row-major)
__device__ __align__(256) __half g_B2h [NMAT * MAT];   // B2 row-major hi
__device__ float g_part[NMAT * 4 * 4];   // [bc][tile 2x2][k: tr2,tr3,tr4,tr5]

// ---------------------------- helpers ---------------------------------------
__device__ __forceinline__ uint32_t smem_u32(const void* p) {
    uint32_t a;
    asm("{ .reg .u64 t; cvta.to.shared.u64 t, %1; cvt.u32.u64 %0, t; }" : "=r"(a) : "l"(p));
    return a;
}
#define CP16(dst, src) asm volatile("cp.async.cg.shared.global [%0], [%1], 16;" :: "r"((uint32_t)(dst)), "l"(src))
#define CP_COMMIT()    asm volatile("cp.async.commit_group;" ::: "memory")
#define CP_WAIT(n)     asm volatile("cp.async.wait_group %0;" :: "n"(n) : "memory")

#define MMA_F16(d, a, b) \
    asm volatile("mma.sync.aligned.m16n8k16.row.col.f32.f16.f16.f32 " \
        "{%0,%1,%2,%3},{%4,%5,%6,%7},{%8,%9},{%0,%1,%2,%3};" \
        : "+f"((d)[0]), "+f"((d)[1]), "+f"((d)[2]), "+f"((d)[3]) \
        : "r"((a)[0]), "r"((a)[1]), "r"((a)[2]), "r"((a)[3]), "r"((b)[0]), "r"((b)[1]))

#define LDSM4(r, addr) \
    asm volatile("ldmatrix.sync.aligned.m8n8.x4.shared.b16 {%0,%1,%2,%3}, [%4];" \
        : "=r"((r)[0]), "=r"((r)[1]), "=r"((r)[2]), "=r"((r)[3]) : "r"(addr))

#define LDSM4T(r, addr) \
    asm volatile("ldmatrix.sync.aligned.m8n8.x4.trans.shared.b16 {%0,%1,%2,%3}, [%4];" \
        : "=r"((r)[0]), "=r"((r)[1]), "=r"((r)[2]), "=r"((r)[3]) : "r"(addr))

__device__ __forceinline__ void split_f16(float v, __half& h, __half& l) {
    h = __float2half_rn(v);
    l = __float2half_rn(v - __half2float(h));
}

// ---------------------------------------------------------------------------
// Conv: x[b,261,261] * w[16,1,6,6] + bias -> g_Ah/g_Al (row-major only)
// ---------------------------------------------------------------------------
__global__ void __launch_bounds__(256) conv_kernel(const float* __restrict__ x,
                                                   const float* __restrict__ w,
                                                   const float* __restrict__ bias) {
    __shared__ float xs[37][38];
    __shared__ float ws[CHN * 36];
    __shared__ float bs[CHN];
    const int b  = blockIdx.z;
    const int bx = blockIdx.x * 32, by = blockIdx.y * 32;
    const int tx = threadIdx.x, ty = threadIdx.y;
    const int tid = ty * 32 + tx;

    for (int i = tid; i < 37 * 37; i += 256) {
        int r = i / 37, c = i % 37;
        xs[r][c] = x[b * NN * NN + (by + r) * NN + (bx + c)];
    }
    for (int i = tid; i < CHN * 36; i += 256) ws[i] = w[i];
    if (tid < CHN) bs[tid] = bias[tid];
    __syncthreads();

    float acc[4][CHN];
#pragma unroll
    for (int r = 0; r < 4; r++)
#pragma unroll
        for (int c = 0; c < CHN; c++) acc[r][c] = bs[c];

#pragma unroll
    for (int p = 0; p < 6; p++) {
#pragma unroll
        for (int q = 0; q < 6; q++) {
            float xv[4];
#pragma unroll
            for (int r = 0; r < 4; r++) xv[r] = xs[ty + 8 * r + p][tx + q];
#pragma unroll
            for (int c = 0; c < CHN; c++) {
                float wv = ws[c * 36 + p * 6 + q];
#pragma unroll
                for (int r = 0; r < 4; r++) acc[r][c] += xv[r] * wv;
            }
        }
    }

#pragma unroll
    for (int c = 0; c < CHN; c++) {
        size_t base = (size_t)(b * CHN + c) * MAT;
#pragma unroll
        for (int r = 0; r < 4; r++) {
            int row = by + ty + 8 * r, col = bx + tx;
            __half h, l; split_f16(acc[r][c], h, l);
            g_Ah[base + row * MM + col] = h;
            g_Al[base + row * MM + col] = l;
        }
    }
}

// ---------------------------------------------------------------------------
// fp16 mma.sync GEMM, 128x128 tile, BK=32, 3-stage cp.async ring.
// IS2=0: C = (Ah+Al)@A (2-term)   -> write B2 hi row-major + tr2 diag partial
// IS2=1: C = Ah@B2h   (1-term)    -> tr3 diag; tr4 = sum C*A^T; tr5 = sum C*B2^T
// Stage-2 has no Al loads/frags -> fewer regs, 2 CTAs/SM.
// ---------------------------------------------------------------------------
#define PADK    40                     // A halves per row (32 + 8 pad); 80B stride
#define PADN    136                    // B halves per row (128 + 8 pad); 272B stride
#define CS_PAD  129
#define SMEM1   87552                  // 3 * (2*10240 + 8704)
#define SMEM2   66176                  // max(3*18944=56832, 66048 Cs + 96 red)

template <bool WITH_AL>
__device__ __forceinline__ void load_stage(uint32_t st,
        const __half* __restrict__ Ah, const __half* __restrict__ Al,
        const __half* __restrict__ Bsrc, int col0, int kb, int tid) {
    const uint32_t offB = WITH_AL ? 20480u : 10240u;
#pragma unroll
    for (int it = 0; it < 2; ++it) {
        int u = it * 256 + tid;          // 0..511
        int rowA = u >> 2, segA = u & 3;
        uint32_t da = (uint32_t)(rowA * (PADK * 2) + segA * 16);
        CP16(st + da, Ah + rowA * MM + kb * 32 + segA * 8);
        if (WITH_AL) CP16(st + 10240u + da, Al + rowA * MM + kb * 32 + segA * 8);
        int rowB = u >> 4, segB = u & 15;
        uint32_t db = (uint32_t)(rowB * (PADN * 2) + segB * 16);
        CP16(st + offB + db, Bsrc + (size_t)(kb * 32 + rowB) * MM + col0 + segB * 8);
    }
}

template <bool IS2>
__global__ void __launch_bounds__(256, IS2 ? 2 : 1) gemm_kernel() {
    constexpr uint32_t OFFB = IS2 ? 10240u : 20480u;
    constexpr uint32_t SB   = IS2 ? 18944u : 29184u;   // stage stride bytes

    extern __shared__ char sm[];
    const uint32_t sbase = smem_u32(sm);
    const int tid  = threadIdx.x;
    const int lane = tid & 31;
    const int w    = tid >> 5;
    const int wm   = w >> 2;            // 0..1 -> 64-row slab
    const int wn   = w & 3;             // 0..3 -> 32-col slab
    const int bc   = blockIdx.z;
    const int row0 = blockIdx.y * 128;
    const int col0 = blockIdx.x * 128;
    const bool diag = (blockIdx.x == blockIdx.y);
    const size_t mbase = (size_t)bc * MAT;

    const __half* Ah = g_Ah + mbase + (size_t)row0 * MM;
    const __half* Al = g_Al + mbase + (size_t)row0 * MM;
    const __half* Bsrc = (IS2 ? g_B2h : g_Ah) + mbase;   // row-major; rows = k

    const uint32_t aRowOff = (uint32_t)(((lane & 15) * PADK + ((lane >> 4) << 3)) * 2)
                           + (uint32_t)(wm * 64 * PADK * 2);
    const int krow_lane = (lane & 7) + ((lane >> 3) & 1) * 8;   // 0..15
    const int ncol_lane = (lane >> 4) * 8;                       // 0 or 8
    const uint32_t bRowOff = (uint32_t)(krow_lane * (PADN * 2)
                           + (wn * 32 + ncol_lane) * 2);

    float acc[4][4][4];
#pragma unroll
    for (int mi = 0; mi < 4; mi++)
#pragma unroll
        for (int ni = 0; ni < 4; ni++)
#pragma unroll
            for (int e = 0; e < 4; e++) acc[mi][ni][e] = 0.f;

    load_stage<!IS2>(sbase + 0 * SB, Ah, Al, Bsrc, col0, 0, tid);
    CP_COMMIT();
    load_stage<!IS2>(sbase + 1 * SB, Ah, Al, Bsrc, col0, 1, tid);
    CP_COMMIT();

    for (int kb = 0; kb < 8; ++kb) {
        if (kb < 7) { CP_WAIT(1); } else { CP_WAIT(0); }
        __syncthreads();
        if (kb + 2 < 8) {
            int s = (kb + 2) % 3;
            load_stage<!IS2>(sbase + s * SB, Ah, Al, Bsrc, col0, kb + 2, tid);
            CP_COMMIT();
        }

        const uint32_t st = sbase + (uint32_t)((kb % 3) * SB);
        const uint32_t aH = st + aRowOff;
        const uint32_t bB = st + OFFB + bRowOff;

#pragma unroll
        for (int ks = 0; ks < 2; ++ks) {
            uint32_t ah[4][4], bq[2][4];
#pragma unroll
            for (int mi = 0; mi < 4; mi++)
                LDSM4(ah[mi], aH + (uint32_t)(mi * 16 * PADK * 2 + ks * 32));
#pragma unroll
            for (int q = 0; q < 2; q++)
                LDSM4T(bq[q], bB + (uint32_t)(ks * 16 * PADN * 2 + q * 32));
#pragma unroll
            for (int mi = 0; mi < 4; mi++)
#pragma unroll
                for (int ni = 0; ni < 4; ni++)
                    MMA_F16(acc[mi][ni], ah[mi], &bq[ni >> 1][(ni & 1) * 2]);
            if (!IS2) {
                uint32_t al[4][4];
#pragma unroll
                for (int mi = 0; mi < 4; mi++)
                    LDSM4(al[mi], st + 10240u + aRowOff + (uint32_t)(mi * 16 * PADK * 2 + ks * 32));
#pragma unroll
                for (int mi = 0; mi < 4; mi++)
#pragma unroll
                    for (int ni = 0; ni < 4; ni++)
                        MMA_F16(acc[mi][ni], al[mi], &bq[ni >> 1][(ni & 1) * 2]);
            }
        }
    }
    __syncthreads();

    // ---------------- epilogue: stage C through smem ----------------
    float* Cs  = (float*)sm;                      // [128][129]
    float* red = (float*)(sm + 66048);
#pragma unroll
    for (int mi = 0; mi < 4; mi++)
#pragma unroll
        for (int ni = 0; ni < 4; ni++) {
            int r = wm * 64 + mi * 16 + (lane >> 2);
            int c = wn * 32 + ni * 8 + (lane & 3) * 2;
            Cs[r * CS_PAD + c]           = acc[mi][ni][0];
            Cs[r * CS_PAD + c + 1]       = acc[mi][ni][1];
            Cs[(r + 8) * CS_PAD + c]     = acc[mi][ni][2];
            Cs[(r + 8) * CS_PAD + c + 1] = acc[mi][ni][3];
        }
    __syncthreads();

    float p0 = 0.f;                     // tr2 (!IS2) or tr3 (IS2), from diag
    float p2 = 0.f, p3 = 0.f;           // tr4, tr5 (IS2 only)

    if (diag && tid < 128) p0 = Cs[tid * CS_PAD + tid];

    if (!IS2) {
        for (int u = tid; u < 8192; u += 256) {
            int i = u >> 6, j2 = (u & 63) * 2;
            float v0 = Cs[i * CS_PAD + j2], v1 = Cs[i * CS_PAD + j2 + 1];
            size_t o = mbase + (size_t)(row0 + i) * MM + col0 + j2;
            *(__half2*)&g_B2h[o] = __halves2half2(__float2half_rn(v0), __float2half_rn(v1));
        }
    } else {
        // tr4 = sum C[r][c] * A[c][r] ; tr5 = sum C[r][c] * B2[c][r]
        for (int u = tid; u < 8192; u += 256) {
            int jj = u >> 6, ii2 = (u & 63) * 2;
            size_t o = mbase + (size_t)(col0 + jj) * MM + row0 + ii2;
            float2 at = __half22float2(*(const __half2*)&g_Ah[o]);
            float2 bt = __half22float2(*(const __half2*)&g_B2h[o]);
            float c0 = Cs[ii2 * CS_PAD + jj];
            float c1 = Cs[(ii2 + 1) * CS_PAD + jj];
            p2 += c0 * at.x + c1 * at.y;      // tr(A^4)
            p3 += c0 * bt.x + c1 * bt.y;      // tr(A^5)
        }
    }

    // deterministic block reduce
#pragma unroll
    for (int off = 16; off; off >>= 1) {
        p0 += __shfl_down_sync(0xFFFFFFFFu, p0, off);
        p2 += __shfl_down_sync(0xFFFFFFFFu, p2, off);
        p3 += __shfl_down_sync(0xFFFFFFFFu, p3, off);
    }
    __syncthreads();
    if (lane == 0) {
        red[w * 3 + 0] = p0; red[w * 3 + 1] = p2; red[w * 3 + 2] = p3;
    }
    __syncthreads();
    if (tid == 0) {
        float s0 = 0.f, s2 = 0.f, s3 = 0.f;
        for (int q = 0; q < 8; q++) {
            s0 += red[q * 3]; s2 += red[q * 3 + 1]; s3 += red[q * 3 + 2];
        }
        int slot = (bc * 4 + (int)(blockIdx.y * 2 + blockIdx.x)) * 4;
        if (!IS2) g_part[slot + 0] = s0;
        else { g_part[slot + 1] = s0; g_part[slot + 2] = s2; g_part[slot + 3] = s3; }
    }
}

// ---------------------------------------------------------------------------
// Combine: out[b] = sum coef[c,i,j] * tr_{i+2}^(j+1) / 65536^(i+j+1)
// ---------------------------------------------------------------------------
__global__ void __launch_bounds__(512) final_kernel(const float* __restrict__ coef,
                                                    float* __restrict__ out) {
    int t = threadIdx.x;
    int b = t >> 4, c = t & 15;
    int bc = b * CHN + c;
    double tr[4];
#pragma unroll
    for (int k = 0; k < 4; k++) {
        float s = 0.f;
#pragma unroll
        for (int tile = 0; tile < 4; tile++) s += g_part[(bc * 4 + tile) * 4 + k];
        tr[k] = (double)s;
    }
    double sum = 0.0;
#pragma unroll
    for (int i = 0; i < 4; i++) {
        double p = tr[i];
        double tp = p;
#pragma unroll
        for (int j = 0; j < 4; j++) {
            double v = ldexp(tp, -16 * (i + j + 1));
            sum += (double)coef[c * 16 + i * 4 + j] * v;
            tp *= p;
        }
    }
#pragma unroll
    for (int off = 8; off; off >>= 1)
        sum += __shfl_down_sync(0xFFFFFFFFu, sum, off, 16);
    if (c == 0) out[b] = (float)sum;
}

extern "C" void kernel_launch(void* const* d_in, const int* in_sizes, int n_in,
                              void* d_out, int out_size) {
    const float* x    = (const float*)d_in[0];
    const float* w    = (const float*)d_in[1];
    const float* bias = (const float*)d_in[2];
    const float* coef = (const float*)d_in[3];
    float* out = (float*)d_out;

    cudaFuncSetAttribute(gemm_kernel<false>, cudaFuncAttributeMaxDynamicSharedMemorySize, SMEM1);
    cudaFuncSetAttribute(gemm_kernel<true>,  cudaFuncAttributeMaxDynamicSharedMemorySize, SMEM2);

    conv_kernel<<<dim3(8, 8, BB), dim3(32, 8)>>>(x, w, bias);
    gemm_kernel<false><<<dim3(2, 2, NMAT), 256, SMEM1>>>();
    gemm_kernel<true> <<<dim3(2, 2, NMAT), 256, SMEM2>>>();
    final_kernel<<<1, 512>>>(coef, out);
}

// round 8
// speedup vs baseline: 1.3884x; 1.3884x over previous
#include <cuda_runtime.h>
#include <cuda_fp16.h>
#include <cstdint>

#define BB   32
#define CHN  16
#define NN   261
#define MM   256
#define MAT  (MM*MM)
#define NMAT (BB*CHN)

// ---------------- scratch (device globals; no allocs allowed) ----------------
__device__ __align__(256) __half g_Ah  [NMAT * MAT];   // feat fp16 (row-major)
__device__ __align__(256) __half g_B2h [NMAT * MAT];   // B2 row-major fp16
__device__ float g_part[NMAT * 4 * 4];   // [bc][tile 2x2][k: tr2,tr3,tr4,tr5]

// ---------------------------- helpers ---------------------------------------
__device__ __forceinline__ uint32_t smem_u32(const void* p) {
    uint32_t a;
    asm("{ .reg .u64 t; cvta.to.shared.u64 t, %1; cvt.u32.u64 %0, t; }" : "=r"(a) : "l"(p));
    return a;
}
#define CP16(dst, src) asm volatile("cp.async.cg.shared.global [%0], [%1], 16;" :: "r"((uint32_t)(dst)), "l"(src))
#define CP_COMMIT()    asm volatile("cp.async.commit_group;" ::: "memory")
#define CP_WAIT(n)     asm volatile("cp.async.wait_group %0;" :: "n"(n) : "memory")

#define MMA_F16(d, a, b) \
    asm volatile("mma.sync.aligned.m16n8k16.row.col.f32.f16.f16.f32 " \
        "{%0,%1,%2,%3},{%4,%5,%6,%7},{%8,%9},{%0,%1,%2,%3};" \
        : "+f"((d)[0]), "+f"((d)[1]), "+f"((d)[2]), "+f"((d)[3]) \
        : "r"((a)[0]), "r"((a)[1]), "r"((a)[2]), "r"((a)[3]), "r"((b)[0]), "r"((b)[1]))

#define LDSM4(r, addr) \
    asm volatile("ldmatrix.sync.aligned.m8n8.x4.shared.b16 {%0,%1,%2,%3}, [%4];" \
        : "=r"((r)[0]), "=r"((r)[1]), "=r"((r)[2]), "=r"((r)[3]) : "r"(addr))

#define LDSM4T(r, addr) \
    asm volatile("ldmatrix.sync.aligned.m8n8.x4.trans.shared.b16 {%0,%1,%2,%3}, [%4];" \
        : "=r"((r)[0]), "=r"((r)[1]), "=r"((r)[2]), "=r"((r)[3]) : "r"(addr))

// ---------------------------------------------------------------------------
// Conv: x[b,261,261] * w[16,1,6,6] + bias -> g_Ah (fp16 row-major)
// ---------------------------------------------------------------------------
__global__ void __launch_bounds__(256) conv_kernel(const float* __restrict__ x,
                                                   const float* __restrict__ w,
                                                   const float* __restrict__ bias) {
    __shared__ float xs[37][38];
    __shared__ float ws[CHN * 36];
    __shared__ float bs[CHN];
    const int b  = blockIdx.z;
    const int bx = blockIdx.x * 32, by = blockIdx.y * 32;
    const int tx = threadIdx.x, ty = threadIdx.y;
    const int tid = ty * 32 + tx;

    for (int i = tid; i < 37 * 37; i += 256) {
        int r = i / 37, c = i % 37;
        xs[r][c] = x[b * NN * NN + (by + r) * NN + (bx + c)];
    }
    for (int i = tid; i < CHN * 36; i += 256) ws[i] = w[i];
    if (tid < CHN) bs[tid] = bias[tid];
    __syncthreads();

    float acc[4][CHN];
#pragma unroll
    for (int r = 0; r < 4; r++)
#pragma unroll
        for (int c = 0; c < CHN; c++) acc[r][c] = bs[c];

#pragma unroll
    for (int p = 0; p < 6; p++) {
#pragma unroll
        for (int q = 0; q < 6; q++) {
            float xv[4];
#pragma unroll
            for (int r = 0; r < 4; r++) xv[r] = xs[ty + 8 * r + p][tx + q];
#pragma unroll
            for (int c = 0; c < CHN; c++) {
                float wv = ws[c * 36 + p * 6 + q];
#pragma unroll
                for (int r = 0; r < 4; r++) acc[r][c] += xv[r] * wv;
            }
        }
    }

#pragma unroll
    for (int c = 0; c < CHN; c++) {
        size_t base = (size_t)(b * CHN + c) * MAT;
#pragma unroll
        for (int r = 0; r < 4; r++) {
            int row = by + ty + 8 * r, col = bx + tx;
            g_Ah[base + row * MM + col] = __float2half_rn(acc[r][c]);
        }
    }
}

// ---------------------------------------------------------------------------
// fp16 mma.sync GEMM, 128x128 tile, BK=32, 4-stage cp.async ring, 1-term.
// IS2=0: C = Ah@Ah   -> write B2 fp16 row-major + tr2 diag partial
// IS2=1: C = Ah@B2h  -> tr3 diag; tr4 = sum C*A^T; tr5 = sum C*B2^T
// ---------------------------------------------------------------------------
#define PADK    40                     // A halves per row (32 + 8 pad); 80B stride
#define PADN    136                    // B halves per row (128 + 8 pad); 272B stride
#define CS_PAD  129
#define OFFB    10240u
#define SB      18944u                 // stage bytes: 128*80 + 32*272
#define GEMM_SMEM 75776                // 4 stages; epilogue needs 66144 < this

__device__ __forceinline__ void load_stage(uint32_t st,
        const __half* __restrict__ Ah, const __half* __restrict__ Bsrc,
        int col0, int kb, int tid) {
#pragma unroll
    for (int it = 0; it < 2; ++it) {
        int u = it * 256 + tid;          // 0..511
        int rowA = u >> 2, segA = u & 3;
        uint32_t da = (uint32_t)(rowA * (PADK * 2) + segA * 16);
        CP16(st + da, Ah + rowA * MM + kb * 32 + segA * 8);
        int rowB = u >> 4, segB = u & 15;
        uint32_t db = (uint32_t)(rowB * (PADN * 2) + segB * 16);
        CP16(st + OFFB + db, Bsrc + (size_t)(kb * 32 + rowB) * MM + col0 + segB * 8);
    }
}

template <bool IS2>
__global__ void __launch_bounds__(256, 2) gemm_kernel() {
    extern __shared__ char sm[];
    const uint32_t sbase = smem_u32(sm);
    const int tid  = threadIdx.x;
    const int lane = tid & 31;
    const int w    = tid >> 5;
    const int wm   = w >> 2;            // 0..1 -> 64-row slab
    const int wn   = w & 3;             // 0..3 -> 32-col slab
    const int bc   = blockIdx.z;
    const int row0 = blockIdx.y * 128;
    const int col0 = blockIdx.x * 128;
    const bool diag = (blockIdx.x == blockIdx.y);
    const size_t mbase = (size_t)bc * MAT;

    const __half* Ah = g_Ah + mbase + (size_t)row0 * MM;
    const __half* Bsrc = (IS2 ? g_B2h : g_Ah) + mbase;   // row-major; rows = k

    const uint32_t aRowOff = (uint32_t)(((lane & 15) * PADK + ((lane >> 4) << 3)) * 2)
                           + (uint32_t)(wm * 64 * PADK * 2);
    const int krow_lane = (lane & 7) + ((lane >> 3) & 1) * 8;   // 0..15
    const int ncol_lane = (lane >> 4) * 8;                       // 0 or 8
    const uint32_t bRowOff = (uint32_t)(krow_lane * (PADN * 2)
                           + (wn * 32 + ncol_lane) * 2);

    float acc[4][4][4];
#pragma unroll
    for (int mi = 0; mi < 4; mi++)
#pragma unroll
        for (int ni = 0; ni < 4; ni++)
#pragma unroll
            for (int e = 0; e < 4; e++) acc[mi][ni][e] = 0.f;

    load_stage(sbase + 0 * SB, Ah, Bsrc, col0, 0, tid); CP_COMMIT();
    load_stage(sbase + 1 * SB, Ah, Bsrc, col0, 1, tid); CP_COMMIT();
    load_stage(sbase + 2 * SB, Ah, Bsrc, col0, 2, tid); CP_COMMIT();

    for (int kb = 0; kb < 8; ++kb) {
        if (kb < 6) { CP_WAIT(2); }
        else if (kb == 6) { CP_WAIT(1); }
        else { CP_WAIT(0); }
        __syncthreads();
        if (kb + 3 < 8) {
            load_stage(sbase + (uint32_t)((kb + 3) & 3) * SB, Ah, Bsrc, col0, kb + 3, tid);
            CP_COMMIT();
        }

        const uint32_t st = sbase + (uint32_t)(kb & 3) * SB;
        const uint32_t aH = st + aRowOff;
        const uint32_t bB = st + OFFB + bRowOff;

#pragma unroll
        for (int ks = 0; ks < 2; ++ks) {
            uint32_t ah[4][4], bq[2][4];
#pragma unroll
            for (int mi = 0; mi < 4; mi++)
                LDSM4(ah[mi], aH + (uint32_t)(mi * 16 * PADK * 2 + ks * 32));
#pragma unroll
            for (int q = 0; q < 2; q++)
                LDSM4T(bq[q], bB + (uint32_t)(ks * 16 * PADN * 2 + q * 32));
#pragma unroll
            for (int mi = 0; mi < 4; mi++)
#pragma unroll
                for (int ni = 0; ni < 4; ni++)
                    MMA_F16(acc[mi][ni], ah[mi], &bq[ni >> 1][(ni & 1) * 2]);
        }
    }
    __syncthreads();

    // ---------------- epilogue: stage C through smem ----------------
    float* Cs  = (float*)sm;                      // [128][129]
    float* red = (float*)(sm + 66048);
#pragma unroll
    for (int mi = 0; mi < 4; mi++)
#pragma unroll
        for (int ni = 0; ni < 4; ni++) {
            int r = wm * 64 + mi * 16 + (lane >> 2);
            int c = wn * 32 + ni * 8 + (lane & 3) * 2;
            Cs[r * CS_PAD + c]           = acc[mi][ni][0];
            Cs[r * CS_PAD + c + 1]       = acc[mi][ni][1];
            Cs[(r + 8) * CS_PAD + c]     = acc[mi][ni][2];
            Cs[(r + 8) * CS_PAD + c + 1] = acc[mi][ni][3];
        }
    __syncthreads();

    float p0 = 0.f;                     // tr2 (!IS2) or tr3 (IS2), from diag
    float p2 = 0.f, p3 = 0.f;           // tr4, tr5 (IS2 only)

    if (diag && tid < 128) p0 = Cs[tid * CS_PAD + tid];

    if (!IS2) {
        for (int u = tid; u < 8192; u += 256) {
            int i = u >> 6, j2 = (u & 63) * 2;
            float v0 = Cs[i * CS_PAD + j2], v1 = Cs[i * CS_PAD + j2 + 1];
            size_t o = mbase + (size_t)(row0 + i) * MM + col0 + j2;
            *(__half2*)&g_B2h[o] = __halves2half2(__float2half_rn(v0), __float2half_rn(v1));
        }
    } else {
        // tr4 = sum C[r][c] * A[c][r] ; tr5 = sum C[r][c] * B2[c][r]
        for (int u = tid; u < 8192; u += 256) {
            int jj = u >> 6, ii2 = (u & 63) * 2;
            size_t o = mbase + (size_t)(col0 + jj) * MM + row0 + ii2;
            float2 at = __half22float2(*(const __half2*)&g_Ah[o]);
            float2 bt = __half22float2(*(const __half2*)&g_B2h[o]);
            float c0 = Cs[ii2 * CS_PAD + jj];
            float c1 = Cs[(ii2 + 1) * CS_PAD + jj];
            p2 += c0 * at.x + c1 * at.y;      // tr(A^4)
            p3 += c0 * bt.x + c1 * bt.y;      // tr(A^5)
        }
    }

    // deterministic block reduce
#pragma unroll
    for (int off = 16; off; off >>= 1) {
        p0 += __shfl_down_sync(0xFFFFFFFFu, p0, off);
        p2 += __shfl_down_sync(0xFFFFFFFFu, p2, off);
        p3 += __shfl_down_sync(0xFFFFFFFFu, p3, off);
    }
    __syncthreads();
    if (lane == 0) {
        red[w * 3 + 0] = p0; red[w * 3 + 1] = p2; red[w * 3 + 2] = p3;
    }
    __syncthreads();
    if (tid == 0) {
        float s0 = 0.f, s2 = 0.f, s3 = 0.f;
        for (int q = 0; q < 8; q++) {
            s0 += red[q * 3]; s2 += red[q * 3 + 1]; s3 += red[q * 3 + 2];
        }
        int slot = (bc * 4 + (int)(blockIdx.y * 2 + blockIdx.x)) * 4;
        if (!IS2) g_part[slot + 0] = s0;
        else { g_part[slot + 1] = s0; g_part[slot + 2] = s2; g_part[slot + 3] = s3; }
    }
}

// ---------------------------------------------------------------------------
// Combine: out[b] = sum coef[c,i,j] * tr_{i+2}^(j+1) / 65536^(i+j+1)
// ---------------------------------------------------------------------------
__global__ void __launch_bounds__(512) final_kernel(const float* __restrict__ coef,
                                                    float* __restrict__ out) {
    int t = threadIdx.x;
    int b = t >> 4, c = t & 15;
    int bc = b * CHN + c;
    double tr[4];
#pragma unroll
    for (int k = 0; k < 4; k++) {
        float s = 0.f;
#pragma unroll
        for (int tile = 0; tile < 4; tile++) s += g_part[(bc * 4 + tile) * 4 + k];
        tr[k] = (double)s;
    }
    double sum = 0.0;
#pragma unroll
    for (int i = 0; i < 4; i++) {
        double p = tr[i];
        double tp = p;
#pragma unroll
        for (int j = 0; j < 4; j++) {
            double v = ldexp(tp, -16 * (i + j + 1));
            sum += (double)coef[c * 16 + i * 4 + j] * v;
            tp *= p;
        }
    }
#pragma unroll
    for (int off = 8; off; off >>= 1)
        sum += __shfl_down_sync(0xFFFFFFFFu, sum, off, 16);
    if (c == 0) out[b] = (float)sum;
}

extern "C" void kernel_launch(void* const* d_in, const int* in_sizes, int n_in,
                              void* d_out, int out_size) {
    const float* x    = (const float*)d_in[0];
    const float* w    = (const float*)d_in[1];
    const float* bias = (const float*)d_in[2];
    const float* coef = (const float*)d_in[3];
    float* out = (float*)d_out;

    cudaFuncSetAttribute(gemm_kernel<false>, cudaFuncAttributeMaxDynamicSharedMemorySize, GEMM_SMEM);
    cudaFuncSetAttribute(gemm_kernel<true>,  cudaFuncAttributeMaxDynamicSharedMemorySize, GEMM_SMEM);

    conv_kernel<<<dim3(8, 8, BB), dim3(32, 8)>>>(x, w, bias);
    gemm_kernel<false><<<dim3(2, 2, NMAT), 256, GEMM_SMEM>>>();
    gemm_kernel<true> <<<dim3(2, 2, NMAT), 256, GEMM_SMEM>>>();
    final_kernel<<<1, 512>>>(coef, out);
}